// round 16
// baseline (speedup 1.0000x reference)
#include <cuda_runtime.h>
#include <cstdint>

// SwitchLinear, SINGLE fused persistent kernel: in-block routing + tf32 GEMM.
// out[t] = (W[route[t]] + Wf) @ x[t] + b[route[t]] + bf ; B=4096, IN=OUT=256, E=16.
//
// PERSISTENT grid of 296 (= 148 SM x 2 CTAs): each block loops over tile
// indices bidx, bidx+296, ... so all work lands in ONE wave (tail wave was
// costing ~2x in R13-R15).
// Tile = (64 tokens, 64 outs). Algebraic split with paired stages: stage s
// (KC=64) loads BOTH W[e] and Wf B-tiles in one cp.async group, computes
// 16 k-steps per barrier reusing the same A fragments. 4 barriers per tile.
// 256 thr, 8 warps (4m x 2n), warp tile 16x32, m16n8k8.tf32, ldmatrix.x4,
// RPAD=68. smem 104448 B -> 2 CTAs/SM.

#define B_TOK   4096
#define E_NUM   16
#define TM      64
#define TN      64
#define KC      64
#define NST     4
#define GRID_X  296
#define RPAD    68
#define A_TILE_F (TM * RPAD)              // 4352 floats
#define B_TILE_F (TN * RPAD)              // 4352 floats
#define DSMEM_BYTES ((2 * A_TILE_F + 4 * B_TILE_F) * 4)   // 104448 B

static __device__ __forceinline__ uint32_t smem_u32(const void* p) {
    uint32_t a;
    asm("{ .reg .u64 t; cvta.to.shared.u64 t, %1; cvt.u32.u64 %0, t; }" : "=r"(a) : "l"(p));
    return a;
}
static __device__ __forceinline__ uint32_t f2tf(float x) {
    uint32_t u;
    asm("cvt.rna.tf32.f32 %0, %1;" : "=r"(u) : "f"(x));
    return u;
}
static __device__ __forceinline__ void mma_tf32(float* d, const uint32_t* a,
                                                uint32_t b0, uint32_t b1) {
    asm volatile(
        "mma.sync.aligned.m16n8k8.row.col.f32.tf32.tf32.f32 "
        "{%0,%1,%2,%3}, {%4,%5,%6,%7}, {%8,%9}, {%0,%1,%2,%3};"
        : "+f"(d[0]), "+f"(d[1]), "+f"(d[2]), "+f"(d[3])
        : "r"(a[0]), "r"(a[1]), "r"(a[2]), "r"(a[3]), "r"(b0), "r"(b1));
}
#define LDSM_X4(r0, r1, r2, r3, addr) \
    asm volatile("ldmatrix.sync.aligned.m8n8.x4.shared.b16 {%0,%1,%2,%3}, [%4];" \
                 : "=r"(r0), "=r"(r1), "=r"(r2), "=r"(r3) : "r"(addr))
#define CP_ASYNC16(dst, src) \
    asm volatile("cp.async.cg.shared.global [%0], [%1], 16;" :: "r"(dst), "l"(src))
#define CP_COMMIT() asm volatile("cp.async.commit_group;" ::: "memory")
#define CP_WAIT0()  asm volatile("cp.async.wait_group 0;" ::: "memory")

__global__ __launch_bounds__(256, 2)
void switch_fused(const int* __restrict__ route,
                  const float* __restrict__ input,
                  const float* __restrict__ weight,
                  const float* __restrict__ wfact,
                  const float* __restrict__ bias,
                  const float* __restrict__ bfact,
                  float* __restrict__ out) {
    extern __shared__ float dsm[];
    float* const A_base = dsm;                           // 2 x A_TILE_F
    float* const B_base = dsm + 2 * A_TILE_F;            // 4 x B_TILE_F (W0,W1,F0,F1)
    __shared__ int   cnt_s[E_NUM];
    __shared__ int   info_s[3];                // e, r0(rank base), tcnt
    __shared__ int   wexcl_s[8];
    __shared__ int   toks_s[TM];
    __shared__ int   ntt_s;
    __shared__ float bias_s[TN];

    const int tid  = threadIdx.x;
    const int wid  = tid >> 5;
    const int lane = tid & 31;

    // ===== routing histogram (ONCE per block) =====
    int r[16];
    #pragma unroll
    for (int i = 0; i < 16; i++) r[i] = route[tid + 256 * i];

    if (tid < E_NUM) cnt_s[tid] = 0;
    __syncthreads();
    #pragma unroll
    for (int i = 0; i < 16; i++) {
        int ei = r[i];
        unsigned m = __match_any_sync(0xffffffffu, ei);
        if ((__ffs(m) - 1) == lane) atomicAdd(&cnt_s[ei], __popc(m));
    }
    __syncthreads();
    if (tid == 0) {
        int tt = 0;
        #pragma unroll
        for (int e2 = 0; e2 < E_NUM; e2++) tt += (cnt_s[e2] + TM - 1) >> 6;
        ntt_s = tt;
    }
    __syncthreads();
    const int ntiles4 = ntt_s * 4;

    // ldmatrix lane addresses (byte offsets, tile-independent)
    const int wm = wid & 3;                    // rows wm*16..+15
    const int wn = wid >> 2;                   // outs wn*32..+31 (within quarter)
    const int a_off_l = ((wm * 16 + (lane & 15)) * RPAD + (lane >> 4) * 4) * 4;
    const int b_row_l = wn * 32 + ((lane >> 4) & 1) * 8 + (lane & 7);
    const int b_off_l = (b_row_l * RPAD + ((lane >> 3) & 1) * 4) * 4;
    uint32_t A_u[2], B_u[4];
    #pragma unroll
    for (int i = 0; i < 2; i++) A_u[i] = smem_u32(A_base + i * A_TILE_F) + a_off_l;
    #pragma unroll
    for (int i = 0; i < 4; i++) B_u[i] = smem_u32(B_base + i * B_TILE_F) + b_off_l;

    const int srow = tid >> 2;                 // staging row 0..63
    const int sq   = tid & 3;                  // 16B quad

    // ===== persistent tile loop =====
    #pragma unroll 1
    for (int bidx = blockIdx.x; bidx < ntiles4; bidx += GRID_X) {
        const int mt = bidx >> 2;
        const int nq = bidx & 3;

        __syncthreads();                       // prev epilogue done with smem
        if (tid == 0) {
            int tt = 0, found = 0, fr0 = 0, fcnt = 0;
            #pragma unroll
            for (int e2 = 0; e2 < E_NUM; e2++) {
                int c2 = cnt_s[e2];
                int nt = (c2 + TM - 1) >> 6;
                if (mt >= tt && mt < tt + nt) {
                    int j = mt - tt;
                    found = e2;
                    fr0 = j * TM;
                    int rem = c2 - j * TM;
                    fcnt = rem < TM ? rem : TM;
                }
                tt += nt;
            }
            info_s[0] = found; info_s[1] = fr0; info_s[2] = fcnt;
        }
        if (tid < TM) toks_s[tid] = 0;         // padding rows -> token 0
        __syncthreads();

        const int e    = info_s[0];
        const int r0   = info_s[1];
        const int tcnt = info_s[2];

        // rank-scan of indicator (route==e), order (tid, i)
        int lc = 0;
        #pragma unroll
        for (int i = 0; i < 16; i++) lc += (r[i] == e) ? 1 : 0;
        int sc = lc;
        #pragma unroll
        for (int d = 1; d < 32; d <<= 1) {
            int v = __shfl_up_sync(0xffffffffu, sc, d);
            if (lane >= d) sc += v;
        }
        if (lane == 31) wexcl_s[wid] = sc;
        __syncthreads();
        if (tid == 0) {
            int acc2 = 0;
            #pragma unroll
            for (int w = 0; w < 8; w++) { int v = wexcl_s[w]; wexcl_s[w] = acc2; acc2 += v; }
        }
        __syncthreads();
        int rank = (sc - lc) + wexcl_s[wid];
        #pragma unroll
        for (int i = 0; i < 16; i++) {
            if (r[i] == e) {
                int rr = rank - r0;
                if (rr >= 0 && rr < TM) toks_s[rr] = tid + 256 * i;
                rank++;
            }
        }
        if (tid < TN)
            bias_s[tid] = bias[e * 256 + nq * TN + tid] + bfact[nq * TN + tid];
        __syncthreads();

        // ===== GEMM for this tile =====
        const float* __restrict__ airow  = input + (size_t)toks_s[srow] * 256;
        const float* __restrict__ wrow_e = weight + (size_t)e * 65536 + (size_t)(nq * TN + srow) * 256;
        const float* __restrict__ wrow_f = wfact + (size_t)(nq * TN + srow) * 256;
        const uint32_t b_dst = smem_u32(B_base) + (uint32_t)((srow * RPAD + sq * 4) * 4);

        auto cpB = [&](int s, int b) {         // W chunk s + Wf chunk s, one group
            const float* srcW = wrow_e + s * KC + sq * 4;
            const float* srcF = wrow_f + s * KC + sq * 4;
            const uint32_t dstW = b_dst + (uint32_t)(b * B_TILE_F * 4);
            const uint32_t dstF = b_dst + (uint32_t)((2 + b) * B_TILE_F * 4);
            #pragma unroll
            for (int j = 0; j < 4; j++)
                CP_ASYNC16(dstW + (uint32_t)(j * 16 * 4), srcW + j * 16);
            #pragma unroll
            for (int j = 0; j < 4; j++)
                CP_ASYNC16(dstF + (uint32_t)(j * 16 * 4), srcF + j * 16);
            CP_COMMIT();
        };
        float4 rA[4];
        auto ldgA = [&](int c) {
            #pragma unroll
            for (int j = 0; j < 4; j++)
                rA[j] = *(const float4*)(airow + c * KC + sq * 4 + j * 16);
        };
        auto stsA = [&](int b) {               // rna-rounded A
            #pragma unroll
            for (int j = 0; j < 4; j++) {
                uint4 cv;
                cv.x = f2tf(rA[j].x); cv.y = f2tf(rA[j].y);
                cv.z = f2tf(rA[j].z); cv.w = f2tf(rA[j].w);
                *(uint4*)(A_base + b * A_TILE_F + srow * RPAD + sq * 4 + j * 16) = cv;
            }
        };

        float acc[4][4];
        #pragma unroll
        for (int an = 0; an < 4; an++)
            #pragma unroll
            for (int j = 0; j < 4; j++) acc[an][j] = 0.0f;

        cpB(0, 0);
        ldgA(0);
        stsA(0);
        ldgA(1);

        #pragma unroll 1
        for (int s = 0; s < NST; s++) {
            CP_WAIT0();                 // B pair (s) landed
            __syncthreads();            // + stsA(s) visible; compute(s-1) done
            if (s + 1 < NST) {
                cpB(s + 1, (s + 1) & 1);
                stsA((s + 1) & 1);
            }
            if (s + 2 < NST) ldgA(s + 2);

            const uint32_t Ab = A_u[s & 1];
            const uint32_t BW = B_u[s & 1];
            const uint32_t BF = B_u[2 + (s & 1)];
            #pragma unroll
            for (int kk = 0; kk < 8; kk++) {
                const uint32_t ko = kk * 32;
                uint32_t a0[4], w0[4], w1[4], f0[4], f1[4];
                LDSM_X4(a0[0], a0[1], a0[2], a0[3], Ab + ko);                    // m16
                LDSM_X4(w0[0], w0[1], w0[2], w0[3], BW + ko);                    // W n0-15
                LDSM_X4(w1[0], w1[1], w1[2], w1[3], BW + ko + 16 * RPAD * 4);    // W n16-31
                mma_tf32(acc[0], a0, w0[0], w0[1]);
                mma_tf32(acc[1], a0, w0[2], w0[3]);
                mma_tf32(acc[2], a0, w1[0], w1[1]);
                mma_tf32(acc[3], a0, w1[2], w1[3]);
                LDSM_X4(f0[0], f0[1], f0[2], f0[3], BF + ko);                    // Wf n0-15
                LDSM_X4(f1[0], f1[1], f1[2], f1[3], BF + ko + 16 * RPAD * 4);    // Wf n16-31
                mma_tf32(acc[0], a0, f0[0], f0[1]);
                mma_tf32(acc[1], a0, f0[2], f0[3]);
                mma_tf32(acc[2], a0, f1[0], f1[1]);
                mma_tf32(acc[3], a0, f1[2], f1[3]);
            }
        }

        // epilogue: bias + store
        const int row0 = wm * 16 + (lane >> 2);
        const int row1 = row0 + 8;
        const bool v0 = row0 < tcnt;
        const bool v1 = row1 < tcnt;
        float* const orow0 = out + (size_t)toks_s[row0] * 256 + nq * TN;
        float* const orow1 = out + (size_t)toks_s[row1] * 256 + nq * TN;
        #pragma unroll
        for (int an = 0; an < 4; an++) {
            const int col = wn * 32 + an * 8 + 2 * (lane & 3);
            const float bx = bias_s[col], by = bias_s[col + 1];
            if (v0) *(float2*)(orow0 + col) = make_float2(acc[an][0] + bx, acc[an][1] + by);
            if (v1) *(float2*)(orow1 + col) = make_float2(acc[an][2] + bx, acc[an][3] + by);
        }
    }
}

// ---------------------------------------------------------------------------
extern "C" void kernel_launch(void* const* d_in, const int* in_sizes, int n_in,
                              void* d_out, int out_size) {
    const float* input  = (const float*)d_in[0];
    const int*   route  = (const int*)d_in[1];
    const float* weight = (const float*)d_in[2];
    const float* wfact  = (const float*)d_in[3];
    const float* bias   = (const float*)d_in[4];
    const float* bfact  = (const float*)d_in[5];
    float* out = (float*)d_out;

    cudaFuncSetAttribute(switch_fused, cudaFuncAttributeMaxDynamicSharedMemorySize,
                         DSMEM_BYTES);

    switch_fused<<<GRID_X, 256, DSMEM_BYTES>>>(route, input, weight, wfact,
                                               bias, bfact, out);
}

// round 17
// speedup vs baseline: 1.3939x; 1.3939x over previous
#include <cuda_runtime.h>
#include <cstdint>

// SwitchLinear, SINGLE fused persistent kernel, NO algebraic split.
// out[t] = (W[route[t]] + Wf) @ x[t] + b[route[t]] + bf ; B=4096, IN=OUT=256, E=16.
//
// B tiles are built IN-KERNEL during staging: LDG W[e] + LDG Wf, FADD,
// cvt.rna.tf32, STS (no prep pass, 1x MMA count). Verified LDSM+mma core.
// Persistent grid 148 (1 CTA/SM, 16 warps): each block loops tiles
// bidx, bidx+148 (~140 tiles -> one wave). Tile = 64 tokens x 128 outs.
// 512 thr, 16 warps (4m x 4n), warp tile 16x32, m16n8k8.tf32, ldmatrix.x4,
// KC=64, 4 stages double-buffered, RPAD=68 (LDSM conflict-free).

#define B_TOK   4096
#define E_NUM   16
#define TM      64
#define TN      128
#define KC      64
#define NST     4
#define GRID_X  148
#define RPAD    68
#define A_TILE_F (TM * RPAD)              // 4352 floats
#define B_TILE_F (TN * RPAD)              // 8704 floats
#define DSMEM_BYTES ((2 * A_TILE_F + 2 * B_TILE_F) * 4)   // 104448 B

static __device__ __forceinline__ uint32_t smem_u32(const void* p) {
    uint32_t a;
    asm("{ .reg .u64 t; cvta.to.shared.u64 t, %1; cvt.u32.u64 %0, t; }" : "=r"(a) : "l"(p));
    return a;
}
static __device__ __forceinline__ uint32_t f2tf(float x) {
    uint32_t u;
    asm("cvt.rna.tf32.f32 %0, %1;" : "=r"(u) : "f"(x));
    return u;
}
static __device__ __forceinline__ void mma_tf32(float* d, const uint32_t* a,
                                                uint32_t b0, uint32_t b1) {
    asm volatile(
        "mma.sync.aligned.m16n8k8.row.col.f32.tf32.tf32.f32 "
        "{%0,%1,%2,%3}, {%4,%5,%6,%7}, {%8,%9}, {%0,%1,%2,%3};"
        : "+f"(d[0]), "+f"(d[1]), "+f"(d[2]), "+f"(d[3])
        : "r"(a[0]), "r"(a[1]), "r"(a[2]), "r"(a[3]), "r"(b0), "r"(b1));
}
#define LDSM_X4(r0, r1, r2, r3, addr) \
    asm volatile("ldmatrix.sync.aligned.m8n8.x4.shared.b16 {%0,%1,%2,%3}, [%4];" \
                 : "=r"(r0), "=r"(r1), "=r"(r2), "=r"(r3) : "r"(addr))

__global__ __launch_bounds__(512, 1)
void switch_fused(const int* __restrict__ route,
                  const float* __restrict__ input,
                  const float* __restrict__ weight,
                  const float* __restrict__ wfact,
                  const float* __restrict__ bias,
                  const float* __restrict__ bfact,
                  float* __restrict__ out) {
    extern __shared__ float dsm[];
    float* const A_base = dsm;                           // 2 x A_TILE_F
    float* const B_base = dsm + 2 * A_TILE_F;            // 2 x B_TILE_F
    __shared__ int   cnt_s[E_NUM];
    __shared__ int   info_s[3];                // e, r0(rank base), tcnt
    __shared__ int   wexcl_s[16];
    __shared__ int   toks_s[TM];
    __shared__ int   ntt_s;
    __shared__ float bias_s[TN];

    const int tid  = threadIdx.x;
    const int wid  = tid >> 5;
    const int lane = tid & 31;

    // ===== routing histogram (ONCE per block) =====
    int r[8];
    #pragma unroll
    for (int i = 0; i < 8; i++) r[i] = route[tid + 512 * i];

    if (tid < E_NUM) cnt_s[tid] = 0;
    __syncthreads();
    #pragma unroll
    for (int i = 0; i < 8; i++) {
        int ei = r[i];
        unsigned m = __match_any_sync(0xffffffffu, ei);
        if ((__ffs(m) - 1) == lane) atomicAdd(&cnt_s[ei], __popc(m));
    }
    __syncthreads();
    if (tid == 0) {
        int tt = 0;
        #pragma unroll
        for (int e2 = 0; e2 < E_NUM; e2++) tt += (cnt_s[e2] + TM - 1) >> 6;
        ntt_s = tt;
    }
    __syncthreads();
    const int ntiles2 = ntt_s * 2;

    // ldmatrix lane addresses (tile-independent, byte offsets)
    const int wm = wid & 3;                    // rows wm*16..+15
    const int wn = wid >> 2;                   // outs wn*32..+31
    const int a_off_l = ((wm * 16 + (lane & 15)) * RPAD + (lane >> 4) * 4) * 4;
    const int b_row_l = wn * 32 + ((lane >> 4) & 1) * 8 + (lane & 7);
    const int b_off_l = (b_row_l * RPAD + ((lane >> 3) & 1) * 4) * 4;
    uint32_t A_u[2], B_u[2];
    #pragma unroll
    for (int i = 0; i < 2; i++) A_u[i] = smem_u32(A_base + i * A_TILE_F) + a_off_l;
    #pragma unroll
    for (int i = 0; i < 2; i++) B_u[i] = smem_u32(B_base + i * B_TILE_F) + b_off_l;

    // staging roles (512 threads)
    const int ar = tid >> 3;                   // A row 0..63
    const int aq = tid & 7;                    // A f4 col (+8 for second)
    const int br = tid >> 2;                   // B row 0..127
    const int bq = tid & 3;                    // B f4 col group (cols bq*4 + j*16)

    // ===== persistent tile loop =====
    #pragma unroll 1
    for (int bidx = blockIdx.x; bidx < ntiles2; bidx += GRID_X) {
        const int mt = bidx >> 1;
        const int nh = bidx & 1;

        __syncthreads();                       // prev tile done with smem
        if (tid == 0) {
            int tt = 0, found = 0, fr0 = 0, fcnt = 0;
            #pragma unroll
            for (int e2 = 0; e2 < E_NUM; e2++) {
                int c2 = cnt_s[e2];
                int nt = (c2 + TM - 1) >> 6;
                if (mt >= tt && mt < tt + nt) {
                    int j = mt - tt;
                    found = e2;
                    fr0 = j * TM;
                    int rem = c2 - j * TM;
                    fcnt = rem < TM ? rem : TM;
                }
                tt += nt;
            }
            info_s[0] = found; info_s[1] = fr0; info_s[2] = fcnt;
        }
        if (tid < TM) toks_s[tid] = 0;         // padding rows -> token 0
        __syncthreads();

        const int e    = info_s[0];
        const int r0   = info_s[1];
        const int tcnt = info_s[2];

        // rank-scan of indicator (route==e), order (tid, i)
        int lc = 0;
        #pragma unroll
        for (int i = 0; i < 8; i++) lc += (r[i] == e) ? 1 : 0;
        int sc = lc;
        #pragma unroll
        for (int d = 1; d < 32; d <<= 1) {
            int v = __shfl_up_sync(0xffffffffu, sc, d);
            if (lane >= d) sc += v;
        }
        if (lane == 31) wexcl_s[wid] = sc;
        __syncthreads();
        if (tid == 0) {
            int acc2 = 0;
            #pragma unroll
            for (int w = 0; w < 16; w++) { int v = wexcl_s[w]; wexcl_s[w] = acc2; acc2 += v; }
        }
        __syncthreads();
        int rank = (sc - lc) + wexcl_s[wid];
        #pragma unroll
        for (int i = 0; i < 8; i++) {
            if (r[i] == e) {
                int rr = rank - r0;
                if (rr >= 0 && rr < TM) toks_s[rr] = tid + 512 * i;
                rank++;
            }
        }
        if (tid < TN)
            bias_s[tid] = bias[e * 256 + nh * TN + tid] + bfact[nh * TN + tid];
        __syncthreads();

        // ===== GEMM for this tile =====
        const float* __restrict__ airow  = input + (size_t)toks_s[ar] * 256;
        const float* __restrict__ wrow_e = weight + (size_t)e * 65536 + (size_t)(nh * TN + br) * 256;
        const float* __restrict__ wrow_f = wfact + (size_t)(nh * TN + br) * 256;

        float4 rA0, rA1, rW[4], rF[4];
        auto ldgA = [&](int c) {
            rA0 = *(const float4*)(airow + c * KC + aq * 4);
            rA1 = *(const float4*)(airow + c * KC + (aq + 8) * 4);
        };
        auto ldgB = [&](int c) {
            #pragma unroll
            for (int j = 0; j < 4; j++) {
                rW[j] = *(const float4*)(wrow_e + c * KC + bq * 4 + j * 16);
                rF[j] = *(const float4*)(wrow_f + c * KC + bq * 4 + j * 16);
            }
        };
        auto stsA = [&](int b) {
            uint4 c0, c1;
            c0.x = f2tf(rA0.x); c0.y = f2tf(rA0.y); c0.z = f2tf(rA0.z); c0.w = f2tf(rA0.w);
            c1.x = f2tf(rA1.x); c1.y = f2tf(rA1.y); c1.z = f2tf(rA1.z); c1.w = f2tf(rA1.w);
            *(uint4*)(A_base + b * A_TILE_F + ar * RPAD + aq * 4)       = c0;
            *(uint4*)(A_base + b * A_TILE_F + ar * RPAD + (aq + 8) * 4) = c1;
        };
        auto stsB = [&](int b) {               // Wsum = rna(W + Wf)
            #pragma unroll
            for (int j = 0; j < 4; j++) {
                uint4 cv;
                cv.x = f2tf(rW[j].x + rF[j].x);
                cv.y = f2tf(rW[j].y + rF[j].y);
                cv.z = f2tf(rW[j].z + rF[j].z);
                cv.w = f2tf(rW[j].w + rF[j].w);
                *(uint4*)(B_base + b * B_TILE_F + br * RPAD + bq * 4 + j * 16) = cv;
            }
        };

        float acc[4][4];
        #pragma unroll
        for (int an = 0; an < 4; an++)
            #pragma unroll
            for (int j = 0; j < 4; j++) acc[an][j] = 0.0f;

        // prologue: stage 0 in smem; stage 1 in regs
        ldgB(0); ldgA(0);
        stsB(0); stsA(0);
        ldgB(1); ldgA(1);
        __syncthreads();

        #pragma unroll 1
        for (int s = 0; s < NST; s++) {
            if (s + 1 < NST) {                 // regs hold stage s+1; other buffer free
                stsB((s + 1) & 1);
                stsA((s + 1) & 1);
            }
            if (s + 2 < NST) {                 // refill regs under compute
                ldgB(s + 2);
                ldgA(s + 2);
            }

            const uint32_t Ab = A_u[s & 1];
            const uint32_t Bb = B_u[s & 1];
            #pragma unroll
            for (int kk = 0; kk < 8; kk++) {
                const uint32_t ko = kk * 32;
                uint32_t a0[4], b0[4], b1r[4];
                LDSM_X4(a0[0], a0[1], a0[2], a0[3], Ab + ko);                     // m16
                LDSM_X4(b0[0], b0[1], b0[2], b0[3], Bb + ko);                     // n 0-15
                LDSM_X4(b1r[0], b1r[1], b1r[2], b1r[3], Bb + ko + 16 * RPAD * 4); // n 16-31
                mma_tf32(acc[0], a0, b0[0], b0[1]);
                mma_tf32(acc[1], a0, b0[2], b0[3]);
                mma_tf32(acc[2], a0, b1r[0], b1r[1]);
                mma_tf32(acc[3], a0, b1r[2], b1r[3]);
            }
            __syncthreads();                   // compute(s) done; sts(s+1) visible
        }

        // epilogue: bias + store
        const int row0 = wm * 16 + (lane >> 2);
        const int row1 = row0 + 8;
        const bool v0 = row0 < tcnt;
        const bool v1 = row1 < tcnt;
        float* const orow0 = out + (size_t)toks_s[row0] * 256 + nh * TN;
        float* const orow1 = out + (size_t)toks_s[row1] * 256 + nh * TN;
        #pragma unroll
        for (int an = 0; an < 4; an++) {
            const int col = wn * 32 + an * 8 + 2 * (lane & 3);
            const float bx = bias_s[col], by = bias_s[col + 1];
            if (v0) *(float2*)(orow0 + col) = make_float2(acc[an][0] + bx, acc[an][1] + by);
            if (v1) *(float2*)(orow1 + col) = make_float2(acc[an][2] + bx, acc[an][3] + by);
        }
    }
}

// ---------------------------------------------------------------------------
extern "C" void kernel_launch(void* const* d_in, const int* in_sizes, int n_in,
                              void* d_out, int out_size) {
    const float* input  = (const float*)d_in[0];
    const int*   route  = (const int*)d_in[1];
    const float* weight = (const float*)d_in[2];
    const float* wfact  = (const float*)d_in[3];
    const float* bias   = (const float*)d_in[4];
    const float* bfact  = (const float*)d_in[5];
    float* out = (float*)d_out;

    cudaFuncSetAttribute(switch_fused, cudaFuncAttributeMaxDynamicSharedMemorySize,
                         DSMEM_BYTES);

    switch_fused<<<GRID_X, 512, DSMEM_BYTES>>>(route, input, weight, wfact,
                                               bias, bfact, out);
}